// round 8
// baseline (speedup 1.0000x reference)
#include <cuda_runtime.h>
#include <cstdint>

#define IH 4096
#define IW 4096
#define OW 4088
#define NTH 128
#define XTILE 512
#define RSTRIP 56
#define ITERS 64          // RSTRIP + 8 input rows per strip
#define RING 16
#define WSEG 144          // floats per warp segment (136 used)
#define RSTRIDE (4 * WSEG) // 576 floats per ring row
#define PF 6

__device__ __forceinline__ uint32_t cvt_tf32(float f) {
    uint32_t r;
    asm("cvt.rna.tf32.f32 %0, %1;" : "=r"(r) : "f"(f));
    return r;
}

__device__ __forceinline__ void mma8(float* d,
                                     uint32_t a0, uint32_t a1, uint32_t a2, uint32_t a3,
                                     uint32_t b0, uint32_t b1) {
    asm("mma.sync.aligned.m16n8k8.row.col.f32.tf32.tf32.f32 "
        "{%0,%1,%2,%3}, {%4,%5,%6,%7}, {%8,%9}, {%0,%1,%2,%3};"
        : "+f"(d[0]), "+f"(d[1]), "+f"(d[2]), "+f"(d[3])
        : "r"(a0), "r"(a1), "r"(a2), "r"(a3), "r"(b0), "r"(b1));
}

__device__ __forceinline__ uint32_t s2u(const void* p) {
    uint32_t a;
    asm("{ .reg .u64 t; cvta.to.shared.u64 t, %1; cvt.u32.u64 %0, t; }" : "=r"(a) : "l"(p));
    return a;
}

__device__ __forceinline__ void cpa16(uint32_t dst, const void* src, uint32_t sz) {
    asm volatile("cp.async.ca.shared.global [%0], [%1], 16, %2;"
                 :: "r"(dst), "l"(src), "r"(sz) : "memory");
}

// warp-private load of input row p's segment (34 x float4 = 136 floats)
#define WARP_LOAD(p) do {                                                        \
    const float* srow = X + (size_t)(ybase + (p)) * IW + xcol;                   \
    const uint32_t drow = smb + (uint32_t)(((p) & (RING-1)) * RSTRIDE + wseg) * 4u; \
    uint32_t sz0 = (xcol + 4*lane + 3 < IW) ? 16u : 0u;                          \
    cpa16(drow + 16u*(uint32_t)lane, srow + 4*lane, sz0);                        \
    if (lane < 2) {                                                              \
        const int j = 32 + lane;                                                 \
        uint32_t sz1 = (xcol + 4*j + 3 < IW) ? 16u : 0u;                         \
        cpa16(drow + 16u*(uint32_t)j, srow + 4*j, sz1);                          \
    }                                                                            \
    asm volatile("cp.async.commit_group;" ::: "memory");                         \
} while (0)

// load + convert the 8 A-fragments of input row R into regs f[8]
#define FRAG_LOAD(f, R) do {                                                     \
    const int _b = ((R) & (RING-1)) * RSTRIDE + wseg + 8*g4 + t4;                \
    f[0] = cvt_tf32(sR[_b]);                                                     \
    f[1] = cvt_tf32(sR[_b + 64]);                                                \
    f[2] = cvt_tf32(sR[_b + 4]);                                                 \
    f[3] = cvt_tf32(sR[_b + 68]);                                                \
    f[4] = cvt_tf32(sR[_b + 8]);                                                 \
    f[5] = cvt_tf32(sR[_b + 72]);                                                \
    f[6] = cvt_tf32(sR[_b + 12]);                                                \
    f[7] = cvt_tf32(sR[_b + 76]);                                                \
} while (0)

// one sliding-window iteration over input row R (RR = R mod 9, static).
// A fragments for row R are already in cur[]; this iteration prefetches
// row R+1's fragments into nxt[] so the MMA stream never waits on LDS.
#define ITER_BODY(R, RR, CLO, CHI) do {                                          \
    if ((R) + PF < ITERS) WARP_LOAD((R) + PF);                                   \
    else asm volatile("cp.async.commit_group;" ::: "memory");                    \
    asm volatile("cp.async.wait_group %0;" :: "n"(PF-1) : "memory");             \
    __syncwarp();                                                                \
    uint32_t nxt[8];                                                             \
    FRAG_LOAD(nxt, (R) + 1);   /* row R+1 complete: see group accounting */      \
    _Pragma("unroll")                                                            \
    for (int ky = 0; ky < 9; ky++) {                                             \
        const int y = (R) - ky;                                                  \
        if ((!(CLO) || y >= 0) && (!(CHI) || y < RSTRIP)) {                      \
            const int s = ((RR) - ky + 9) % 9;                                   \
            mma8(acc[s], cur[0], cur[1], cur[2], cur[3], bf[ky][0][0], bf[ky][0][1]); \
            mma8(acc[s], cur[4], cur[5], cur[6], cur[7], bf[ky][1][0], bf[ky][1][1]); \
        }                                                                        \
    }                                                                            \
    {   const int y = (R) - 8;                                                   \
        if (!(CLO) || y >= 0) {                                                  \
            const int s = ((RR) + 1) % 9;                                        \
            const int gy = ybase + y;                                            \
            const int gxa = xcol + 8*g4 + 2*t4;                                  \
            if (gxa < OW) {                                                      \
                float2 v; v.x = acc[s][0]; v.y = acc[s][1];                      \
                *(float2*)(Out + (size_t)gy*OW + gxa) = v;                       \
            }                                                                    \
            if (gxa + 64 < OW) {                                                 \
                float2 v; v.x = acc[s][2]; v.y = acc[s][3];                      \
                *(float2*)(Out + (size_t)gy*OW + gxa + 64) = v;                  \
            }                                                                    \
            _Pragma("unroll")                                                    \
            for (int q = 0; q < 4; q++) acc[s][q] = bias;                        \
        }                                                                        \
    }                                                                            \
    _Pragma("unroll")                                                            \
    for (int q = 0; q < 8; q++) cur[q] = nxt[q];                                 \
} while (0)

__global__ void __launch_bounds__(NTH)
conv9x9_mma(const float* __restrict__ X, const float* __restrict__ Kw,
            const float* __restrict__ Bias, float* __restrict__ Out)
{
    __shared__ __align__(16) float sR[RING * RSTRIDE];

    const int tid  = threadIdx.x;
    const int lane = tid & 31;
    const int g4   = lane >> 2;   // groupID
    const int t4   = lane & 3;    // thread-in-group
    const int wseg = (tid >> 5) * WSEG;           // smem segment base (floats)
    const int xb   = blockIdx.x * XTILE;
    const int xcol = xb + (tid >> 5) * 128;       // warp's first output column
    const int ybase = blockIdx.y * RSTRIP;
    const uint32_t smb = s2u(sR);

    const float bias = Bias[0];

    // Toeplitz B fragments: B[k,n] = w[ky, k - n], k = 8c + t4 (+4), n = g4
    uint32_t bf[9][2][2];
    #pragma unroll
    for (int ky = 0; ky < 9; ky++) {
        #pragma unroll
        for (int c = 0; c < 2; c++) {
            const int kx0 = 8*c + t4 - g4;
            const int kx1 = kx0 + 4;
            float w0 = (kx0 >= 0 && kx0 < 9) ? Kw[ky*9 + kx0] : 0.0f;
            float w1 = (kx1 >= 0 && kx1 < 9) ? Kw[ky*9 + kx1] : 0.0f;
            bf[ky][c][0] = cvt_tf32(w0);
            bf[ky][c][1] = cvt_tf32(w1);
        }
    }

    float acc[9][4];
    #pragma unroll
    for (int s = 0; s < 9; s++)
        #pragma unroll
        for (int q = 0; q < 4; q++) acc[s][q] = bias;

    // prologue: prefetch rows 0..PF-1 (warp-private, one commit group each)
    #pragma unroll
    for (int p = 0; p < PF; p++) WARP_LOAD(p);

    // wait for row 0 and preload its fragments
    asm volatile("cp.async.wait_group %0;" :: "n"(PF-1) : "memory");
    __syncwarp();
    uint32_t cur[8];
    FRAG_LOAD(cur, 0);

    // block 0: r = 0..8 (y>=0 checks)
    #pragma unroll
    for (int rr = 0; rr < 9; rr++) ITER_BODY(rr, rr, true, false);

    // middle blocks: r = 9..53, all y in [1,54) valid
    for (int rb = 9; rb <= 45; rb += 9) {
        #pragma unroll
        for (int rr = 0; rr < 9; rr++) ITER_BODY(rb + rr, rr, false, false);
    }

    // block at 54: r = 54..62 (y < RSTRIP checks)
    #pragma unroll
    for (int rr = 0; rr < 9; rr++) ITER_BODY(54 + rr, rr, false, true);

    // tail: r = 63 (63 mod 9 == 0)
    ITER_BODY(63, 0, false, true);
}

extern "C" void kernel_launch(void* const* d_in, const int* in_sizes, int n_in,
                              void* d_out, int out_size)
{
    const float* X    = (const float*)d_in[0];
    const float* Kw   = (const float*)d_in[1];
    const float* Bias = (const float*)d_in[2];
    float* Out        = (float*)d_out;

    dim3 grid(8, 73);   // 8 x-tiles of 512 cols, 73 y-strips of 56 rows
    dim3 block(NTH);
    conv9x9_mma<<<grid, block>>>(X, Kw, Bias, Out);
}